// round 9
// baseline (speedup 1.0000x reference)
#include <cuda_runtime.h>
#include <cuda_fp16.h>
#include <cstdint>

#define NODES 100000
#define BATCH 4096
#define NF1 25
#define NF2 10

// ---------------- device scratch (16B-aligned) ----------------
__device__ __align__(16) float  g_A32[(size_t)NODES * 256];  // emb tf32-rounded, K-permuted
__device__ __align__(16) __half g_Rh[(size_t)NODES * 512];   // R rows: [Q(256) | P(256)] fp16
__device__ __align__(16) float  g_Wcat[512 * 256];           // [Wa;Wb] rounded, K-permuted
__device__ __align__(16) float  g_W2r[256 * 512];            // W2 rounded, K-permuted
__device__ __align__(16) float  g_W3r[64 * 256];             // W3 rounded, K-permuted
__device__ __align__(16) float  g_C[BATCH * 512];            // [h0|h1mean] rounded, K-permuted
__device__ __align__(16) float  g_E[BATCH * 256];            // layer-2 out rounded, K-permuted

// ---------------- PTX helpers ----------------
__device__ __forceinline__ uint32_t smem_u32(const void* p) {
    uint32_t a; asm("{ .reg .u64 t; cvta.to.shared.u64 t, %1; cvt.u32.u64 %0, t; }" : "=r"(a) : "l"(p));
    return a;
}
__device__ __forceinline__ void cp_async16(uint32_t dst, const void* src) {
    asm volatile("cp.async.cg.shared.global [%0], [%1], 16;" :: "r"(dst), "l"(src));
}
__device__ __forceinline__ void cp_commit() { asm volatile("cp.async.commit_group;" ::: "memory"); }
template <int N>
__device__ __forceinline__ void cp_wait() { asm volatile("cp.async.wait_group %0;" :: "n"(N) : "memory"); }

__device__ __forceinline__ uint32_t cvt_tf32(float f) {
    uint32_t u; asm("cvt.rna.tf32.f32 %0, %1;" : "=r"(u) : "f"(f)); return u;
}
__device__ __forceinline__ float round_tf32(float f) { return __uint_as_float(cvt_tf32(f)); }

__device__ __forceinline__ void mma_tf32(float* d, const uint32_t* a, const uint32_t* b) {
    asm volatile("mma.sync.aligned.m16n8k8.row.col.f32.tf32.tf32.f32 "
        "{%0,%1,%2,%3},{%4,%5,%6,%7},{%8,%9},{%0,%1,%2,%3};"
        : "+f"(d[0]), "+f"(d[1]), "+f"(d[2]), "+f"(d[3])
        : "r"(a[0]), "r"(a[1]), "r"(a[2]), "r"(a[3]), "r"(b[0]), "r"(b[1]));
}

// K-perm: src col c -> position 2*(c&3)+((c&7)>>2) within its 8-group.
__device__ __forceinline__ int permc(int c) { return (c & ~7) + 2 * (c & 3) + ((c & 7) >> 2); }

// ---------------- fused conversion: weights + emb ----------------
__global__ __launch_bounds__(256) void conv_all(const float* __restrict__ W1,
                                                const float* __restrict__ W2,
                                                const float* __restrict__ W3,
                                                const float* __restrict__ emb) {
    int idx = blockIdx.x * 256 + threadIdx.x;
    if (idx < 131072) {              // Wcat[512,256]
        int n = idx >> 8, p = idx & 255;
        int c = (p & ~7) + ((p & 7) >> 1) + (p & 1) * 4;
        float w = (n < 256) ? W1[n * 512 + c] : W1[(n - 256) * 512 + 256 + c];
        g_Wcat[idx] = round_tf32(w);
    } else if (idx < 262144) {       // W2r[256,512]
        int j = idx - 131072;
        int n = j >> 9, p = j & 511;
        int c = (p & ~7) + ((p & 7) >> 1) + (p & 1) * 4;
        g_W2r[j] = round_tf32(W2[n * 512 + c]);
    } else if (idx < 278528) {       // W3r[64,256]
        int j = idx - 262144;
        int n = j >> 8, p = j & 255;
        int c = (p & ~7) + ((p & 7) >> 1) + (p & 1) * 4;
        g_W3r[j] = round_tf32(W3[n * 256 + c]);
    } else {                         // emb: one 8-col group per thread
        int i8 = idx - 278528;       // 0 .. NODES*32-1
        const float4* s = (const float4*)emb + (size_t)i8 * 2;
        float4 a = s[0], b = s[1];
        float4 d0 = make_float4(round_tf32(a.x), round_tf32(b.x), round_tf32(a.y), round_tf32(b.y));
        float4 d1 = make_float4(round_tf32(a.z), round_tf32(b.z), round_tf32(a.w), round_tf32(b.w));
        float4* d = (float4*)g_A32 + (size_t)i8 * 2;
        d[0] = d0; d[1] = d1;
    }
}

// ---------------- big GEMM: g_Rh[100000,512] = g_A32 @ g_Wcat^T (tf32, fp16 out) ----------------
// 128x128 CTA tile, 4-stage pipeline, k-chunk 16, prefetch distance 3.
// Row stride 24 floats: LDS.64 banks qr*12+qc mod 16 all distinct -> conflict-free.
static constexpr int BIG_RS    = 24;                 // floats per smem row
static constexpr int BIG_ASTG  = 128 * BIG_RS;       // 3072 floats
static constexpr int BIG_STGF  = 2 * BIG_ASTG;       // A+B per stage = 6144 floats
static constexpr int BIG_SMEM  = 4 * BIG_STGF * 4;   // 98304 bytes

__global__ __launch_bounds__(256, 2) void tf32_gemm_big() {
    extern __shared__ float sm[];
    const int tid = threadIdx.x;
    const int lane = tid & 31, wid = tid >> 5;
    const int wm = wid & 1, wn = wid >> 1;
    const int qr = lane >> 2, qc = lane & 3;
    const int m0 = blockIdx.y * 128, n0 = blockIdx.x * 128;
    const float* __restrict__ A = g_A32;
    const float* __restrict__ B = g_Wcat;

    float acc[4][4][4];
#pragma unroll
    for (int mt = 0; mt < 4; mt++)
#pragma unroll
        for (int nt = 0; nt < 4; nt++)
#pragma unroll
            for (int r = 0; r < 4; r++) acc[mt][nt][r] = 0.f;

    const uint32_t smA = smem_u32(sm);
    const int rowL = tid >> 2, segL = tid & 3;           // loader row/seg (i=0)
    const int rowH = (tid + 256) >> 2, segH = tid & 3;   // i=1 slot
    int mL = m0 + rowL; if (mL > NODES - 1) mL = NODES - 1;
    int mH = m0 + rowH; if (mH > NODES - 1) mH = NODES - 1;
    const int nL = n0 + rowL, nH = n0 + rowH;

    auto load_chunk = [&](int c, int s) {
        const int k0 = c * 16;
        const uint32_t base = smA + s * (BIG_STGF * 4);
        cp_async16(base + rowL * 96 + segL * 16, A + (size_t)mL * 256 + k0 + segL * 4);
        cp_async16(base + rowH * 96 + segH * 16, A + (size_t)mH * 256 + k0 + segH * 4);
        const uint32_t bb = base + BIG_ASTG * 4;
        cp_async16(bb + rowL * 96 + segL * 16, B + (size_t)nL * 256 + k0 + segL * 4);
        cp_async16(bb + rowH * 96 + segH * 16, B + (size_t)nH * 256 + k0 + segH * 4);
        cp_commit();
    };

    load_chunk(0, 0);
    load_chunk(1, 1);
    load_chunk(2, 2);

    const int NKC = 16;
    for (int c = 0; c < NKC; ++c) {
        const int s = c & 3;
        if (c + 3 < NKC) load_chunk(c + 3, (c + 3) & 3);
        if (c + 3 < NKC) cp_wait<3>();
        else if (c + 2 < NKC) cp_wait<2>();
        else if (c + 1 < NKC) cp_wait<1>();
        else cp_wait<0>();
        __syncthreads();

        const float* As = sm + s * BIG_STGF;
        const float* Bs = As + BIG_ASTG;
#pragma unroll
        for (int kk = 0; kk < 2; kk++) {
            uint32_t af[4][4], bf[4][2];
#pragma unroll
            for (int mt = 0; mt < 4; mt++) {
                const float* p = As + (wm * 64 + mt * 16 + qr) * BIG_RS + kk * 8 + 2 * qc;
                float2 v0 = *(const float2*)p;
                float2 v1 = *(const float2*)(p + 8 * BIG_RS);
                af[mt][0] = __float_as_uint(v0.x);
                af[mt][2] = __float_as_uint(v0.y);
                af[mt][1] = __float_as_uint(v1.x);
                af[mt][3] = __float_as_uint(v1.y);
            }
#pragma unroll
            for (int nt = 0; nt < 4; nt++) {
                const float* p = Bs + (wn * 32 + nt * 8 + qr) * BIG_RS + kk * 8 + 2 * qc;
                float2 v = *(const float2*)p;
                bf[nt][0] = __float_as_uint(v.x);
                bf[nt][1] = __float_as_uint(v.y);
            }
#pragma unroll
            for (int mt = 0; mt < 4; mt++)
#pragma unroll
                for (int nt = 0; nt < 4; nt++)
                    mma_tf32(acc[mt][nt], af[mt], bf[nt]);
        }
        __syncthreads();
    }

    // epilogue -> g_Rh fp16 (N = 512)
#pragma unroll
    for (int mt = 0; mt < 4; mt++) {
#pragma unroll
        for (int nt = 0; nt < 4; nt++) {
            int rg = m0 + wm * 64 + mt * 16 + qr;
            int cg = n0 + wn * 32 + nt * 8 + qc * 2;
#pragma unroll
            for (int h = 0; h < 2; h++) {
                int r = rg + h * 8;
                if (r < NODES) {
                    *(__half2*)(g_Rh + (size_t)r * 512 + cg) =
                        __floats2half2_rn(acc[mt][nt][h * 2], acc[mt][nt][h * 2 + 1]);
                }
            }
        }
    }
}

// ---------------- small tf32 GEMM (layers 2/3): C = A[M,K] @ Bm[N,K]^T ----------------
// TM=64 x 128, 2-stage chunk 32, stride 40. OUT_MODE: 0 = fp32 float2, 1 = permuted+rounded scalar.
template <bool RELU, int OUT_MODE>
__global__ __launch_bounds__(256, 2) void tf32_gemm_small(
    const float* __restrict__ A, const float* __restrict__ Bm, float* __restrict__ C0,
    int M, int N, int K)
{
    constexpr int ASZ = 64 * 40;
    constexpr int BSZ = 128 * 40;
    extern __shared__ float sm[];
    const int tid = threadIdx.x;
    const int lane = tid & 31, wid = tid >> 5;
    const int wm = wid & 1, wn = wid >> 1;
    const int qr = lane >> 2, qc = lane & 3;
    const int m0 = blockIdx.y * 64, n0 = blockIdx.x * 128;

    float acc[2][4][4];
#pragma unroll
    for (int mt = 0; mt < 2; mt++)
#pragma unroll
        for (int nt = 0; nt < 4; nt++)
#pragma unroll
            for (int r = 0; r < 4; r++) acc[mt][nt][r] = 0.f;

    const uint32_t smA = smem_u32(sm);
    const int NKC = K >> 5;

    auto load_tile = [&](int c, int s) {
        const int k0 = c * 32;
        const uint32_t aBase = smA + s * (ASZ * 4);
        const uint32_t bBase = smA + (2 * ASZ + s * BSZ) * 4;
        {
            int row = tid >> 3, seg = tid & 7;       // 64 rows x 8 segs / 256 thr -> 2 rows per 16 thr... 256 slots of 512 -> 2 loops
#pragma unroll
            for (int i = 0; i < 2; i++) {
                int idx = tid + i * 256;
                row = idx >> 3; seg = idx & 7;
                if (row < 64) {
                    int m = m0 + row; if (m > M - 1) m = M - 1;
                    cp_async16(aBase + row * 160 + seg * 16, A + (size_t)m * K + k0 + seg * 4);
                }
            }
        }
#pragma unroll
        for (int i = 0; i < 4; i++) {
            int idx = tid + i * 256;
            int row = idx >> 3, seg = idx & 7;
            int n = n0 + row; if (n > N - 1) n = N - 1;
            cp_async16(bBase + row * 160 + seg * 16, Bm + (size_t)n * K + k0 + seg * 4);
        }
        cp_commit();
    };

    load_tile(0, 0);

    for (int c = 0; c < NKC; ++c) {
        const int s = c & 1;
        if (c + 1 < NKC) { load_tile(c + 1, s ^ 1); cp_wait<1>(); }
        else cp_wait<0>();
        __syncthreads();

        const float* As = sm + s * ASZ;
        const float* Bs = sm + 2 * ASZ + s * BSZ;
#pragma unroll
        for (int kk = 0; kk < 4; kk++) {
            uint32_t af[2][4], bf[4][2];
#pragma unroll
            for (int mt = 0; mt < 2; mt++) {
                const float* p = As + (wm * 32 + mt * 16 + qr) * 40 + kk * 8 + 2 * qc;
                float2 v0 = *(const float2*)p;
                float2 v1 = *(const float2*)(p + 8 * 40);
                af[mt][0] = __float_as_uint(v0.x);
                af[mt][2] = __float_as_uint(v0.y);
                af[mt][1] = __float_as_uint(v1.x);
                af[mt][3] = __float_as_uint(v1.y);
            }
#pragma unroll
            for (int nt = 0; nt < 4; nt++) {
                const float* p = Bs + (wn * 32 + nt * 8 + qr) * 40 + kk * 8 + 2 * qc;
                float2 v = *(const float2*)p;
                bf[nt][0] = __float_as_uint(v.x);
                bf[nt][1] = __float_as_uint(v.y);
            }
#pragma unroll
            for (int mt = 0; mt < 2; mt++)
#pragma unroll
                for (int nt = 0; nt < 4; nt++)
                    mma_tf32(acc[mt][nt], af[mt], bf[nt]);
        }
        __syncthreads();
    }

#pragma unroll
    for (int mt = 0; mt < 2; mt++) {
#pragma unroll
        for (int nt = 0; nt < 4; nt++) {
            int rg = m0 + wm * 32 + mt * 16 + qr;
            int cg = n0 + wn * 32 + nt * 8 + qc * 2;
            if (cg >= N) continue;
#pragma unroll
            for (int h = 0; h < 2; h++) {
                int r = rg + h * 8;
                if (r >= M) continue;
                float a = acc[mt][nt][h * 2], b = acc[mt][nt][h * 2 + 1];
                if (RELU) { a = fmaxf(a, 0.f); b = fmaxf(b, 0.f); }
                if (OUT_MODE == 1) {
                    C0[(size_t)r * N + permc(cg)]     = round_tf32(a);
                    C0[(size_t)r * N + permc(cg + 1)] = round_tf32(b);
                } else {
                    *(float2*)(C0 + (size_t)r * N + cg) = make_float2(a, b);
                }
            }
        }
    }
}

// ---------------- gather + reduce (unchanged from R8) ----------------
__global__ __launch_bounds__(128) void gather_kernel(
    const int* __restrict__ T0, const int* __restrict__ T1, const int* __restrict__ T2)
{
    __shared__ __align__(16) float   redA[3][32][8];
    __shared__ __align__(16) __half2 redP[3][32][4];
    __shared__ const char* sP1[NF1];
    __shared__ const char* sP2[NF1 * NF2];
    const int b = blockIdx.x;
    const int t = threadIdx.x;
    const char* Rb = (const char*)g_Rh;

    if (t < NF1) sP1[t] = Rb + (size_t)T1[b * NF1 + t] * 1024;
    for (int i = t; i < NF1 * NF2; i += 128) sP2[i] = Rb + (size_t)T2[b * NF1 * NF2 + i] * 1024;
    __syncthreads();

    const int cg = t & 31, fg = t >> 5;
    const int qoff = cg * 16;
    const int poff = 512 + cg * 16;
    const int f0 = (fg == 0) ? 0 : (1 + fg * 6);
    const int f1 = 1 + (fg + 1) * 6;

    __half2 pacc[4];
#pragma unroll
    for (int i = 0; i < 4; i++) pacc[i] = __floats2half2_rn(0.f, 0.f);
    for (int f = f0; f < f1; f++) {
        uint4 v = *(const uint4*)(sP1[f] + poff);
        pacc[0] = __hadd2(pacc[0], *(__half2*)&v.x);
        pacc[1] = __hadd2(pacc[1], *(__half2*)&v.y);
        pacc[2] = __hadd2(pacc[2], *(__half2*)&v.z);
        pacc[3] = __hadd2(pacc[3], *(__half2*)&v.w);
    }

    float a[8];
#pragma unroll
    for (int i = 0; i < 8; i++) a[i] = 0.f;
#pragma unroll 1
    for (int f = f0; f < f1; f++) {
        uint4 qv = *(const uint4*)(sP1[f] + qoff);
        __half2 sA[4], sB[4];
#pragma unroll
        for (int i = 0; i < 4; i++) { sA[i] = __floats2half2_rn(0.f, 0.f); sB[i] = sA[i]; }
#pragma unroll
        for (int j = 0; j < NF2; j += 2) {
            uint4 u = *(const uint4*)(sP2[f * NF2 + j] + poff);
            uint4 w = *(const uint4*)(sP2[f * NF2 + j + 1] + poff);
            sA[0] = __hadd2(sA[0], *(__half2*)&u.x);
            sA[1] = __hadd2(sA[1], *(__half2*)&u.y);
            sA[2] = __hadd2(sA[2], *(__half2*)&u.z);
            sA[3] = __hadd2(sA[3], *(__half2*)&u.w);
            sB[0] = __hadd2(sB[0], *(__half2*)&w.x);
            sB[1] = __hadd2(sB[1], *(__half2*)&w.y);
            sB[2] = __hadd2(sB[2], *(__half2*)&w.z);
            sB[3] = __hadd2(sB[3], *(__half2*)&w.w);
        }
        const uint32_t* qh = (const uint32_t*)&qv;
#pragma unroll
        for (int i = 0; i < 4; i++) {
            float2 s0 = __half22float2(sA[i]);
            float2 s1 = __half22float2(sB[i]);
            float2 q  = __half22float2(*(__half2*)&qh[i]);
            float sx = s0.x + s1.x, sy = s0.y + s1.y;
            a[2 * i]     += fmaxf(fmaf(sx, 0.1f, q.x), 0.f);
            a[2 * i + 1] += fmaxf(fmaf(sy, 0.1f, q.y), 0.f);
        }
    }

    if (fg > 0) {
#pragma unroll
        for (int i = 0; i < 4; i++) redP[fg - 1][cg][i] = pacc[i];
        *(float4*)&redA[fg - 1][cg][0] = make_float4(a[0], a[1], a[2], a[3]);
        *(float4*)&redA[fg - 1][cg][4] = make_float4(a[4], a[5], a[6], a[7]);
    }
    __syncthreads();
    if (fg == 0) {
#pragma unroll
        for (int r = 0; r < 3; r++) {
#pragma unroll
            for (int i = 0; i < 4; i++) pacc[i] = __hadd2(pacc[i], redP[r][cg][i]);
            float4 x = *(const float4*)&redA[r][cg][0];
            float4 y = *(const float4*)&redA[r][cg][4];
            a[0] += x.x; a[1] += x.y; a[2] += x.z; a[3] += x.w;
            a[4] += y.x; a[5] += y.y; a[6] += y.z; a[7] += y.w;
        }
        uint4 q0v = *(const uint4*)(Rb + (size_t)T0[b] * 1024 + qoff);
        const uint32_t* qh = (const uint32_t*)&q0v;
        float h0[8], h1[8];
#pragma unroll
        for (int i = 0; i < 4; i++) {
            float2 p = __half22float2(pacc[i]);
            float2 q = __half22float2(*(__half2*)&qh[i]);
            h0[2 * i]     = fmaxf(fmaf(p.x, 1.f / 25.f, q.x), 0.f);
            h0[2 * i + 1] = fmaxf(fmaf(p.y, 1.f / 25.f, q.y), 0.f);
            h1[2 * i]     = a[2 * i] * (1.f / 25.f);
            h1[2 * i + 1] = a[2 * i + 1] * (1.f / 25.f);
        }
        float* Cr = g_C + b * 512 + cg * 8;
        *(float4*)Cr = make_float4(round_tf32(h0[0]), round_tf32(h0[4]),
                                   round_tf32(h0[1]), round_tf32(h0[5]));
        *(float4*)(Cr + 4) = make_float4(round_tf32(h0[2]), round_tf32(h0[6]),
                                         round_tf32(h0[3]), round_tf32(h0[7]));
        *(float4*)(Cr + 256) = make_float4(round_tf32(h1[0]), round_tf32(h1[4]),
                                           round_tf32(h1[1]), round_tf32(h1[5]));
        *(float4*)(Cr + 260) = make_float4(round_tf32(h1[2]), round_tf32(h1[6]),
                                           round_tf32(h1[3]), round_tf32(h1[7]));
    }
}

// ---------------- launch ----------------
static constexpr int SM64 = 2 * (64 * 40 + 128 * 40) * 4;   // 61440

extern "C" void kernel_launch(void* const* d_in, const int* in_sizes, int n_in,
                              void* d_out, int out_size)
{
    const int* T0 = (const int*)d_in[0];
    const int* T1 = (const int*)d_in[1];
    const int* T2 = (const int*)d_in[2];
    const float* emb = (const float*)d_in[3];
    const float* W1 = (const float*)d_in[4];
    const float* W2 = (const float*)d_in[5];
    const float* W3 = (const float*)d_in[6];
    float* out = (float*)d_out;

    void *pW2, *pW3, *pC, *pE;
    cudaGetSymbolAddress(&pW2, g_W2r);
    cudaGetSymbolAddress(&pW3, g_W3r);
    cudaGetSymbolAddress(&pC, g_C);
    cudaGetSymbolAddress(&pE, g_E);

    cudaFuncSetAttribute((const void*)tf32_gemm_big,
                         cudaFuncAttributeMaxDynamicSharedMemorySize, BIG_SMEM);
    cudaFuncSetAttribute((const void*)tf32_gemm_small<true, 1>,
                         cudaFuncAttributeMaxDynamicSharedMemorySize, SM64);
    cudaFuncSetAttribute((const void*)tf32_gemm_small<false, 0>,
                         cudaFuncAttributeMaxDynamicSharedMemorySize, SM64);

    // 1) round+permute weights and emb (single fused kernel)
    conv_all<<<(278528 + NODES * 32) / 256, 256>>>(W1, W2, W3, emb);

    // 2) R = emb @ Wcat^T -> g_Rh fp16 (4-stage pipelined)
    {
        dim3 grid(4, (NODES + 127) / 128);
        tf32_gemm_big<<<grid, 256, BIG_SMEM>>>();
    }

    // 3) gather + reduce -> g_C [4096, 512]
    gather_kernel<<<BATCH, 128>>>(T0, T1, T2);

    // 4) E = relu(C @ W2^T) : [4096, 256], K=512
    {
        dim3 grid(2, BATCH / 64);
        tf32_gemm_small<true, 1><<<grid, 256, SM64>>>(
            (const float*)pC, (const float*)pW2, (float*)pE, BATCH, 256, 512);
    }

    // 5) scores = E @ W3^T : [4096, 64], K=256
    {
        dim3 grid(1, BATCH / 64);
        tf32_gemm_small<false, 0><<<grid, 256, SM64>>>(
            (const float*)pE, (const float*)pW3, out, BATCH, 64, 256);
    }
}

// round 12
// speedup vs baseline: 1.4046x; 1.4046x over previous
#include <cuda_runtime.h>
#include <cuda_fp16.h>
#include <cstdint>

#define NODES 100000
#define BATCH 4096
#define NF1 25
#define NF2 10

// ---------------- device scratch (16B-aligned) ----------------
__device__ __align__(16) __half g_Ah[(size_t)NODES * 256];   // emb fp16, k16-permuted
__device__ __align__(16) __half g_Wch[512 * 256];            // [Wa;Wb] fp16, k16-permuted
__device__ __align__(16) __half g_Rh[(size_t)NODES * 512];   // R rows: [Q(256) | P(256)] fp16
__device__ __align__(16) float  g_W2r[256 * 512];            // W2 tf32-rounded, 8-permuted
__device__ __align__(16) float  g_W3r[64 * 256];             // W3 tf32-rounded, 8-permuted
__device__ __align__(16) float  g_C[BATCH * 512];            // [h0|h1mean] rounded, 8-permuted
__device__ __align__(16) float  g_E[BATCH * 256];            // layer-2 out rounded, 8-permuted

// ---------------- PTX helpers ----------------
__device__ __forceinline__ uint32_t smem_u32(const void* p) {
    uint32_t a; asm("{ .reg .u64 t; cvta.to.shared.u64 t, %1; cvt.u32.u64 %0, t; }" : "=r"(a) : "l"(p));
    return a;
}
__device__ __forceinline__ void cp_async16(uint32_t dst, const void* src) {
    asm volatile("cp.async.cg.shared.global [%0], [%1], 16;" :: "r"(dst), "l"(src));
}
__device__ __forceinline__ void cp_commit() { asm volatile("cp.async.commit_group;" ::: "memory"); }
template <int N>
__device__ __forceinline__ void cp_wait() { asm volatile("cp.async.wait_group %0;" :: "n"(N) : "memory"); }

__device__ __forceinline__ uint32_t cvt_tf32(float f) {
    uint32_t u; asm("cvt.rna.tf32.f32 %0, %1;" : "=r"(u) : "f"(f)); return u;
}
__device__ __forceinline__ float round_tf32(float f) { return __uint_as_float(cvt_tf32(f)); }

__device__ __forceinline__ void mma_tf32(float* d, const uint32_t* a, const uint32_t* b) {
    asm volatile("mma.sync.aligned.m16n8k8.row.col.f32.tf32.tf32.f32 "
        "{%0,%1,%2,%3},{%4,%5,%6,%7},{%8,%9},{%0,%1,%2,%3};"
        : "+f"(d[0]), "+f"(d[1]), "+f"(d[2]), "+f"(d[3])
        : "r"(a[0]), "r"(a[1]), "r"(a[2]), "r"(a[3]), "r"(b[0]), "r"(b[1]));
}
__device__ __forceinline__ void mma_f16(float* d, const uint32_t* a, const uint32_t* b) {
    asm volatile("mma.sync.aligned.m16n8k16.row.col.f32.f16.f16.f32 "
        "{%0,%1,%2,%3},{%4,%5,%6,%7},{%8,%9},{%0,%1,%2,%3};"
        : "+f"(d[0]), "+f"(d[1]), "+f"(d[2]), "+f"(d[3])
        : "r"(a[0]), "r"(a[1]), "r"(a[2]), "r"(a[3]), "r"(b[0]), "r"(b[1]));
}

// tf32 8-group perm (layers 2/3): src col c -> pos 2*(c&3)+((c&7)>>2).
__device__ __forceinline__ int permc(int c) { return (c & ~7) + 2 * (c & 3) + ((c & 7) >> 2); }
// fp16 16-group perm: dst position p holds src col:
__device__ __forceinline__ int srcpos16(int p) { return 2 * (p >> 2) + (p & 1) + ((p >> 1) & 1) * 8; }

// ---------------- fused conversion ----------------
// idx space: Wch 131072 | W2r 131072 | W3r 16384 | emb 16-groups NODES*16
__global__ __launch_bounds__(256) void conv_all(const float* __restrict__ W1,
                                                const float* __restrict__ W2,
                                                const float* __restrict__ W3,
                                                const float* __restrict__ emb) {
    int idx = blockIdx.x * 256 + threadIdx.x;
    if (idx < 131072) {              // Wch[512,256] fp16, k16-permuted
        int n = idx >> 8, p = idx & 255;
        int c = (p & ~15) + srcpos16(p & 15);
        float w = (n < 256) ? W1[n * 512 + c] : W1[(n - 256) * 512 + 256 + c];
        g_Wch[idx] = __float2half(w);
    } else if (idx < 262144) {       // W2r[256,512] tf32, 8-permuted
        int j = idx - 131072;
        int n = j >> 9, p = j & 511;
        int c = (p & ~7) + ((p & 7) >> 1) + (p & 1) * 4;
        g_W2r[j] = round_tf32(W2[n * 512 + c]);
    } else if (idx < 278528) {       // W3r[64,256] tf32, 8-permuted
        int j = idx - 262144;
        int n = j >> 8, p = j & 255;
        int c = (p & ~7) + ((p & 7) >> 1) + (p & 1) * 4;
        g_W3r[j] = round_tf32(W3[n * 256 + c]);
    } else {                         // emb -> fp16, k16-permuted; one 16-group per thread
        int gid = idx - 278528;      // 0 .. NODES*16-1
        if (gid < NODES * 16) {
            int row = gid >> 4, g = gid & 15;
            const float* s = emb + (size_t)row * 256 + g * 16;
            float v[16];
#pragma unroll
            for (int q = 0; q < 4; q++) *(float4*)&v[q * 4] = *(const float4*)(s + q * 4);
            __half out[16];
#pragma unroll
            for (int p = 0; p < 16; p++) out[p] = __float2half(v[srcpos16(p)]);
            uint4* d = (uint4*)(g_Ah + (size_t)row * 256 + g * 16);
            d[0] = *(uint4*)&out[0];
            d[1] = *(uint4*)&out[8];
        }
    }
}

// ---------------- big GEMM (fp16 m16n8k16): g_Rh = g_Ah @ g_Wch^T ----------------
// 128x128 CTA tile, k-chunk 64 (4 chunks), 2-stage cp.async.
// smem rows: 64 halves data + 16 pad = 160B -> conflict-free LDS.64 (banks 8qr+2qc distinct/phase).
static constexpr int BH_TILEB = 128 * 160;      // 20480 B per matrix per stage
static constexpr int BH_STGB  = 2 * BH_TILEB;   // 40960
static constexpr int BH_SMEM  = 2 * BH_STGB;    // 81920

__global__ __launch_bounds__(256, 2) void f16_gemm_big() {
    extern __shared__ char smc[];
    const uint32_t smA = smem_u32(smc);
    const int tid = threadIdx.x;
    const int lane = tid & 31, wid = tid >> 5;
    const int wm = wid & 1, wn = wid >> 1;
    const int qr = lane >> 2, qc = lane & 3;
    const int m0 = blockIdx.y * 128, n0 = blockIdx.x * 128;

    float acc[4][4][4];
#pragma unroll
    for (int mt = 0; mt < 4; mt++)
#pragma unroll
        for (int nt = 0; nt < 4; nt++)
#pragma unroll
            for (int r = 0; r < 4; r++) acc[mt][nt][r] = 0.f;

    auto load_chunk = [&](int c, int s) {
        const int k0 = c * 64;                   // halves
        const uint32_t base = smA + s * BH_STGB;
#pragma unroll
        for (int i = 0; i < 4; i++) {
            int idx = tid + i * 256;
            int row = idx >> 3, seg = idx & 7;
            int m = m0 + row; if (m > NODES - 1) m = NODES - 1;
            int n = n0 + row; if (n > 511) n = 511;
            cp_async16(base + row * 160 + seg * 16,
                       g_Ah + (size_t)m * 256 + k0 + seg * 8);
            cp_async16(base + BH_TILEB + row * 160 + seg * 16,
                       g_Wch + (size_t)n * 256 + k0 + seg * 8);
        }
        cp_commit();
    };

    load_chunk(0, 0);

    for (int c = 0; c < 4; ++c) {
        const int s = c & 1;
        if (c + 1 < 4) { load_chunk(c + 1, s ^ 1); cp_wait<1>(); }
        else cp_wait<0>();
        __syncthreads();

        const char* As = smc + s * BH_STGB;
        const char* Bs = As + BH_TILEB;
#pragma unroll
        for (int kk = 0; kk < 4; kk++) {
            uint32_t af[4][4], bf[4][2];
#pragma unroll
            for (int mt = 0; mt < 4; mt++) {
                const char* p = As + (wm * 64 + mt * 16 + qr) * 160 + kk * 32 + qc * 8;
                uint2 v0 = *(const uint2*)p;             // row qr:   (a0 | a2)
                uint2 v1 = *(const uint2*)(p + 8 * 160); // row qr+8: (a1 | a3)
                af[mt][0] = v0.x; af[mt][1] = v1.x;
                af[mt][2] = v0.y; af[mt][3] = v1.y;
            }
#pragma unroll
            for (int nt = 0; nt < 4; nt++) {
                const char* p = Bs + (wn * 32 + nt * 8 + qr) * 160 + kk * 32 + qc * 8;
                uint2 v = *(const uint2*)p;              // (b0 | b1)
                bf[nt][0] = v.x; bf[nt][1] = v.y;
            }
#pragma unroll
            for (int mt = 0; mt < 4; mt++)
#pragma unroll
                for (int nt = 0; nt < 4; nt++)
                    mma_f16(acc[mt][nt], af[mt], bf[nt]);
        }
        __syncthreads();
    }

    // epilogue -> g_Rh fp16 (N = 512)
#pragma unroll
    for (int mt = 0; mt < 4; mt++) {
#pragma unroll
        for (int nt = 0; nt < 4; nt++) {
            int rg = m0 + wm * 64 + mt * 16 + qr;
            int cg = n0 + wn * 32 + nt * 8 + qc * 2;
#pragma unroll
            for (int h = 0; h < 2; h++) {
                int r = rg + h * 8;
                if (r < NODES) {
                    *(__half2*)(g_Rh + (size_t)r * 512 + cg) =
                        __floats2half2_rn(acc[mt][nt][h * 2], acc[mt][nt][h * 2 + 1]);
                }
            }
        }
    }
}

// ---------------- small tf32 GEMM (layers 2/3): C = A[M,K] @ Bm[N,K]^T ----------------
// TM x 128 tile, 2-stage k32, stride 40. OUT_MODE: 0 = fp32 float2, 1 = permuted+rounded scalar.
template <int TM, bool RELU, int OUT_MODE>
__global__ __launch_bounds__(256, 2) void tf32_gemm_small(
    const float* __restrict__ A, const float* __restrict__ Bm, float* __restrict__ C0,
    int M, int N, int K)
{
    constexpr int MT  = TM / 32;
    constexpr int ASZ = TM * 40;
    constexpr int BSZ = 128 * 40;
    extern __shared__ float sm[];
    const int tid = threadIdx.x;
    const int lane = tid & 31, wid = tid >> 5;
    const int wm = wid & 1, wn = wid >> 1;
    const int qr = lane >> 2, qc = lane & 3;
    const int m0 = blockIdx.y * TM, n0 = blockIdx.x * 128;

    float acc[MT][4][4];
#pragma unroll
    for (int mt = 0; mt < MT; mt++)
#pragma unroll
        for (int nt = 0; nt < 4; nt++)
#pragma unroll
            for (int r = 0; r < 4; r++) acc[mt][nt][r] = 0.f;

    const uint32_t smA = smem_u32(sm);
    const int NKC = K >> 5;

    auto load_tile = [&](int c, int s) {
        const int k0 = c * 32;
        const uint32_t aBase = smA + s * (ASZ * 4);
        const uint32_t bBase = smA + (2 * ASZ + s * BSZ) * 4;
#pragma unroll
        for (int i = 0; i < TM / 32; i++) {
            int idx = tid + i * 256;
            int row = idx >> 3, seg = idx & 7;
            int m = m0 + row; if (m > M - 1) m = M - 1;
            cp_async16(aBase + row * 160 + seg * 16, A + (size_t)m * K + k0 + seg * 4);
        }
#pragma unroll
        for (int i = 0; i < 4; i++) {
            int idx = tid + i * 256;
            int row = idx >> 3, seg = idx & 7;
            int n = n0 + row; if (n > N - 1) n = N - 1;
            cp_async16(bBase + row * 160 + seg * 16, Bm + (size_t)n * K + k0 + seg * 4);
        }
        cp_commit();
    };

    load_tile(0, 0);

    for (int c = 0; c < NKC; ++c) {
        const int s = c & 1;
        if (c + 1 < NKC) { load_tile(c + 1, s ^ 1); cp_wait<1>(); }
        else cp_wait<0>();
        __syncthreads();

        const float* As = sm + s * ASZ;
        const float* Bs = sm + 2 * ASZ + s * BSZ;
#pragma unroll
        for (int kk = 0; kk < 4; kk++) {
            uint32_t af[MT][4], bf[4][2];
#pragma unroll
            for (int mt = 0; mt < MT; mt++) {
                const float* p = As + (wm * (TM / 2) + mt * 16 + qr) * 40 + kk * 8 + 2 * qc;
                float2 v0 = *(const float2*)p;
                float2 v1 = *(const float2*)(p + 8 * 40);
                af[mt][0] = __float_as_uint(v0.x);
                af[mt][2] = __float_as_uint(v0.y);
                af[mt][1] = __float_as_uint(v1.x);
                af[mt][3] = __float_as_uint(v1.y);
            }
#pragma unroll
            for (int nt = 0; nt < 4; nt++) {
                const float* p = Bs + (wn * 32 + nt * 8 + qr) * 40 + kk * 8 + 2 * qc;
                float2 v = *(const float2*)p;
                bf[nt][0] = __float_as_uint(v.x);
                bf[nt][1] = __float_as_uint(v.y);
            }
#pragma unroll
            for (int mt = 0; mt < MT; mt++)
#pragma unroll
                for (int nt = 0; nt < 4; nt++)
                    mma_tf32(acc[mt][nt], af[mt], bf[nt]);
        }
        __syncthreads();
    }

#pragma unroll
    for (int mt = 0; mt < MT; mt++) {
#pragma unroll
        for (int nt = 0; nt < 4; nt++) {
            int rg = m0 + wm * (TM / 2) + mt * 16 + qr;
            int cg = n0 + wn * 32 + nt * 8 + qc * 2;
            if (cg >= N) continue;
#pragma unroll
            for (int h = 0; h < 2; h++) {
                int r = rg + h * 8;
                if (r >= M) continue;
                float a = acc[mt][nt][h * 2], b = acc[mt][nt][h * 2 + 1];
                if (RELU) { a = fmaxf(a, 0.f); b = fmaxf(b, 0.f); }
                if (OUT_MODE == 1) {
                    C0[(size_t)r * N + permc(cg)]     = round_tf32(a);
                    C0[(size_t)r * N + permc(cg + 1)] = round_tf32(b);
                } else {
                    *(float2*)(C0 + (size_t)r * N + cg) = make_float2(a, b);
                }
            }
        }
    }
}

// ---------------- gather + reduce (unchanged from R8) ----------------
__global__ __launch_bounds__(128) void gather_kernel(
    const int* __restrict__ T0, const int* __restrict__ T1, const int* __restrict__ T2)
{
    __shared__ __align__(16) float   redA[3][32][8];
    __shared__ __align__(16) __half2 redP[3][32][4];
    __shared__ const char* sP1[NF1];
    __shared__ const char* sP2[NF1 * NF2];
    const int b = blockIdx.x;
    const int t = threadIdx.x;
    const char* Rb = (const char*)g_Rh;

    if (t < NF1) sP1[t] = Rb + (size_t)T1[b * NF1 + t] * 1024;
    for (int i = t; i < NF1 * NF2; i += 128) sP2[i] = Rb + (size_t)T2[b * NF1 * NF2 + i] * 1024;
    __syncthreads();

    const int cg = t & 31, fg = t >> 5;
    const int qoff = cg * 16;
    const int poff = 512 + cg * 16;
    const int f0 = (fg == 0) ? 0 : (1 + fg * 6);
    const int f1 = 1 + (fg + 1) * 6;

    __half2 pacc[4];
#pragma unroll
    for (int i = 0; i < 4; i++) pacc[i] = __floats2half2_rn(0.f, 0.f);
    for (int f = f0; f < f1; f++) {
        uint4 v = *(const uint4*)(sP1[f] + poff);
        pacc[0] = __hadd2(pacc[0], *(__half2*)&v.x);
        pacc[1] = __hadd2(pacc[1], *(__half2*)&v.y);
        pacc[2] = __hadd2(pacc[2], *(__half2*)&v.z);
        pacc[3] = __hadd2(pacc[3], *(__half2*)&v.w);
    }

    float a[8];
#pragma unroll
    for (int i = 0; i < 8; i++) a[i] = 0.f;
#pragma unroll 1
    for (int f = f0; f < f1; f++) {
        uint4 qv = *(const uint4*)(sP1[f] + qoff);
        __half2 sA[4], sB[4];
#pragma unroll
        for (int i = 0; i < 4; i++) { sA[i] = __floats2half2_rn(0.f, 0.f); sB[i] = sA[i]; }
#pragma unroll
        for (int j = 0; j < NF2; j += 2) {
            uint4 u = *(const uint4*)(sP2[f * NF2 + j] + poff);
            uint4 w = *(const uint4*)(sP2[f * NF2 + j + 1] + poff);
            sA[0] = __hadd2(sA[0], *(__half2*)&u.x);
            sA[1] = __hadd2(sA[1], *(__half2*)&u.y);
            sA[2] = __hadd2(sA[2], *(__half2*)&u.z);
            sA[3] = __hadd2(sA[3], *(__half2*)&u.w);
            sB[0] = __hadd2(sB[0], *(__half2*)&w.x);
            sB[1] = __hadd2(sB[1], *(__half2*)&w.y);
            sB[2] = __hadd2(sB[2], *(__half2*)&w.z);
            sB[3] = __hadd2(sB[3], *(__half2*)&w.w);
        }
        const uint32_t* qh = (const uint32_t*)&qv;
#pragma unroll
        for (int i = 0; i < 4; i++) {
            float2 s0 = __half22float2(sA[i]);
            float2 s1 = __half22float2(sB[i]);
            float2 q  = __half22float2(*(__half2*)&qh[i]);
            float sx = s0.x + s1.x, sy = s0.y + s1.y;
            a[2 * i]     += fmaxf(fmaf(sx, 0.1f, q.x), 0.f);
            a[2 * i + 1] += fmaxf(fmaf(sy, 0.1f, q.y), 0.f);
        }
    }

    if (fg > 0) {
#pragma unroll
        for (int i = 0; i < 4; i++) redP[fg - 1][cg][i] = pacc[i];
        *(float4*)&redA[fg - 1][cg][0] = make_float4(a[0], a[1], a[2], a[3]);
        *(float4*)&redA[fg - 1][cg][4] = make_float4(a[4], a[5], a[6], a[7]);
    }
    __syncthreads();
    if (fg == 0) {
#pragma unroll
        for (int r = 0; r < 3; r++) {
#pragma unroll
            for (int i = 0; i < 4; i++) pacc[i] = __hadd2(pacc[i], redP[r][cg][i]);
            float4 x = *(const float4*)&redA[r][cg][0];
            float4 y = *(const float4*)&redA[r][cg][4];
            a[0] += x.x; a[1] += x.y; a[2] += x.z; a[3] += x.w;
            a[4] += y.x; a[5] += y.y; a[6] += y.z; a[7] += y.w;
        }
        uint4 q0v = *(const uint4*)(Rb + (size_t)T0[b] * 1024 + qoff);
        const uint32_t* qh = (const uint32_t*)&q0v;
        float h0[8], h1[8];
#pragma unroll
        for (int i = 0; i < 4; i++) {
            float2 p = __half22float2(pacc[i]);
            float2 q = __half22float2(*(__half2*)&qh[i]);
            h0[2 * i]     = fmaxf(fmaf(p.x, 1.f / 25.f, q.x), 0.f);
            h0[2 * i + 1] = fmaxf(fmaf(p.y, 1.f / 25.f, q.y), 0.f);
            h1[2 * i]     = a[2 * i] * (1.f / 25.f);
            h1[2 * i + 1] = a[2 * i + 1] * (1.f / 25.f);
        }
        float* Cr = g_C + b * 512 + cg * 8;
        *(float4*)Cr = make_float4(round_tf32(h0[0]), round_tf32(h0[4]),
                                   round_tf32(h0[1]), round_tf32(h0[5]));
        *(float4*)(Cr + 4) = make_float4(round_tf32(h0[2]), round_tf32(h0[6]),
                                         round_tf32(h0[3]), round_tf32(h0[7]));
        *(float4*)(Cr + 256) = make_float4(round_tf32(h1[0]), round_tf32(h1[4]),
                                           round_tf32(h1[1]), round_tf32(h1[5]));
        *(float4*)(Cr + 260) = make_float4(round_tf32(h1[2]), round_tf32(h1[6]),
                                           round_tf32(h1[3]), round_tf32(h1[7]));
    }
}

// ---------------- launch ----------------
static constexpr int SM32 = 2 * (32 * 40 + 128 * 40) * 4;   // 51200

extern "C" void kernel_launch(void* const* d_in, const int* in_sizes, int n_in,
                              void* d_out, int out_size)
{
    const int* T0 = (const int*)d_in[0];
    const int* T1 = (const int*)d_in[1];
    const int* T2 = (const int*)d_in[2];
    const float* emb = (const float*)d_in[3];
    const float* W1 = (const float*)d_in[4];
    const float* W2 = (const float*)d_in[5];
    const float* W3 = (const float*)d_in[6];
    float* out = (float*)d_out;

    void *pW2, *pW3, *pC, *pE;
    cudaGetSymbolAddress(&pW2, g_W2r);
    cudaGetSymbolAddress(&pW3, g_W3r);
    cudaGetSymbolAddress(&pC, g_C);
    cudaGetSymbolAddress(&pE, g_E);

    cudaFuncSetAttribute((const void*)f16_gemm_big,
                         cudaFuncAttributeMaxDynamicSharedMemorySize, BH_SMEM);
    cudaFuncSetAttribute((const void*)tf32_gemm_small<32, true, 1>,
                         cudaFuncAttributeMaxDynamicSharedMemorySize, SM32);
    cudaFuncSetAttribute((const void*)tf32_gemm_small<32, false, 0>,
                         cudaFuncAttributeMaxDynamicSharedMemorySize, SM32);

    // 1) convert weights (fp16 k16-perm / tf32 8-perm) + emb (fp16 k16-perm)
    conv_all<<<(278528 + NODES * 16 + 255) / 256, 256>>>(W1, W2, W3, emb);

    // 2) R = emb @ Wcat^T -> g_Rh fp16 (fp16 m16n8k16 tensor cores)
    {
        dim3 grid(4, (NODES + 127) / 128);
        f16_gemm_big<<<grid, 256, BH_SMEM>>>();
    }

    // 3) gather + reduce -> g_C [4096, 512]
    gather_kernel<<<BATCH, 128>>>(T0, T1, T2);

    // 4) E = relu(C @ W2^T) : [4096, 256], K=512
    {
        dim3 grid(2, BATCH / 32);
        tf32_gemm_small<32, true, 1><<<grid, 256, SM32>>>(
            (const float*)pC, (const float*)pW2, (float*)pE, BATCH, 256, 512);
    }

    // 5) scores = E @ W3^T : [4096, 64], K=256
    {
        dim3 grid(1, BATCH / 32);
        tf32_gemm_small<32, false, 0><<<grid, 256, SM32>>>(
            (const float*)pE, (const float*)pW3, out, BATCH, 64, 256);
    }
}

// round 13
// speedup vs baseline: 1.5656x; 1.1146x over previous
#include <cuda_runtime.h>
#include <cuda_fp16.h>
#include <cstdint>

#define NODES 100000
#define BATCH 4096
#define NF1 25
#define NF2 10

// ---------------- device scratch (16B-aligned) ----------------
__device__ __align__(16) __half g_Ah[(size_t)NODES * 256];   // emb fp16, k16-permuted
__device__ __align__(16) __half g_Wch[512 * 256];            // [Wa;Wb] fp16, k16-permuted
__device__ __align__(16) __half g_Rh[(size_t)NODES * 512];   // R rows: [Q(256) | P(256)] fp16
__device__ __align__(16) __half g_W2h[256 * 512];            // W2 fp16, k16-permuted
__device__ __align__(16) __half g_W3h[64 * 256];             // W3 fp16, k16-permuted
__device__ __align__(16) __half g_Ch[BATCH * 512];           // [h0|h1mean] fp16, k16-permuted
__device__ __align__(16) __half g_Eh[BATCH * 256];           // layer-2 out fp16, k16-permuted

// ---------------- PTX helpers ----------------
__device__ __forceinline__ uint32_t smem_u32(const void* p) {
    uint32_t a; asm("{ .reg .u64 t; cvta.to.shared.u64 t, %1; cvt.u32.u64 %0, t; }" : "=r"(a) : "l"(p));
    return a;
}
__device__ __forceinline__ void cp_async16(uint32_t dst, const void* src) {
    asm volatile("cp.async.cg.shared.global [%0], [%1], 16;" :: "r"(dst), "l"(src));
}
__device__ __forceinline__ void cp_commit() { asm volatile("cp.async.commit_group;" ::: "memory"); }
template <int N>
__device__ __forceinline__ void cp_wait() { asm volatile("cp.async.wait_group %0;" :: "n"(N) : "memory"); }

__device__ __forceinline__ void mma_f16(float* d, const uint32_t* a, const uint32_t* b) {
    asm volatile("mma.sync.aligned.m16n8k16.row.col.f32.f16.f16.f32 "
        "{%0,%1,%2,%3},{%4,%5,%6,%7},{%8,%9},{%0,%1,%2,%3};"
        : "+f"(d[0]), "+f"(d[1]), "+f"(d[2]), "+f"(d[3])
        : "r"(a[0]), "r"(a[1]), "r"(a[2]), "r"(a[3]), "r"(b[0]), "r"(b[1]));
}

// fp16 16-group perm: dst position p holds src col srcpos16(p); fwd16 is its inverse.
__device__ __forceinline__ int srcpos16(int p) { return 2 * (p >> 2) + (p & 1) + ((p >> 1) & 1) * 8; }
__device__ __forceinline__ int fwd16(int c) {
    return (c & ~15) | (((c & 7) >> 1) << 2) | (((c >> 3) & 1) << 1) | (c & 1);
}

// ---------------- fused conversion ----------------
// idx space: Wch 131072 | W2h 131072 | W3h 16384 | emb 16-groups NODES*16
__global__ __launch_bounds__(256) void conv_all(const float* __restrict__ W1,
                                                const float* __restrict__ W2,
                                                const float* __restrict__ W3,
                                                const float* __restrict__ emb) {
    int idx = blockIdx.x * 256 + threadIdx.x;
    if (idx < 131072) {              // Wch[512,256] fp16, k16-permuted
        int n = idx >> 8, p = idx & 255;
        int c = (p & ~15) + srcpos16(p & 15);
        float w = (n < 256) ? W1[n * 512 + c] : W1[(n - 256) * 512 + 256 + c];
        g_Wch[idx] = __float2half(w);
    } else if (idx < 262144) {       // W2h[256,512] fp16, k16-permuted
        int j = idx - 131072;
        int n = j >> 9, p = j & 511;
        int c = (p & ~15) + srcpos16(p & 15);
        g_W2h[j] = __float2half(W2[n * 512 + c]);
    } else if (idx < 278528) {       // W3h[64,256] fp16, k16-permuted
        int j = idx - 262144;
        int n = j >> 8, p = j & 255;
        int c = (p & ~15) + srcpos16(p & 15);
        g_W3h[j] = __float2half(W3[n * 256 + c]);
    } else {                         // emb -> fp16, k16-permuted; one 16-group per thread
        int gid = idx - 278528;      // 0 .. NODES*16-1
        if (gid < NODES * 16) {
            int row = gid >> 4, g = gid & 15;
            const float* s = emb + (size_t)row * 256 + g * 16;
            float v[16];
#pragma unroll
            for (int q = 0; q < 4; q++) *(float4*)&v[q * 4] = *(const float4*)(s + q * 4);
            __half out[16];
#pragma unroll
            for (int p = 0; p < 16; p++) out[p] = __float2half(v[srcpos16(p)]);
            uint4* d = (uint4*)(g_Ah + (size_t)row * 256 + g * 16);
            d[0] = *(uint4*)&out[0];
            d[1] = *(uint4*)&out[8];
        }
    }
}

// ---------------- big GEMM (fp16 m16n8k16): g_Rh = g_Ah @ g_Wch^T ----------------
// 128(M) x 256(N) CTA tile, 8 warps in 2x4, warp tile 64x64. k-chunk 64 halves, 2 stages.
// smem rows 160B (64 halves + 16B pad) -> conflict-free LDS.64.
static constexpr int BG_A_B   = 128 * 160;            // 20480 A bytes per stage
static constexpr int BG_B_B   = 256 * 160;            // 40960 B bytes per stage
static constexpr int BG_STGB  = BG_A_B + BG_B_B;      // 61440
static constexpr int BG_SMEM  = 2 * BG_STGB;          // 122880

__global__ __launch_bounds__(256, 1) void f16_gemm_big() {
    extern __shared__ char smc[];
    const uint32_t smA = smem_u32(smc);
    const int tid = threadIdx.x;
    const int lane = tid & 31, wid = tid >> 5;
    const int wm = wid & 1, wn = wid >> 1;      // 2 x 4
    const int qr = lane >> 2, qc = lane & 3;
    const int m0 = blockIdx.y * 128, n0 = blockIdx.x * 256;

    float acc[4][8][4];
#pragma unroll
    for (int mt = 0; mt < 4; mt++)
#pragma unroll
        for (int nt = 0; nt < 8; nt++)
#pragma unroll
            for (int r = 0; r < 4; r++) acc[mt][nt][r] = 0.f;

    auto load_chunk = [&](int c, int s) {
        const int k0 = c * 64;
        const uint32_t base = smA + s * BG_STGB;
#pragma unroll
        for (int i = 0; i < 4; i++) {           // A: 128 rows x 8 segs = 1024 slots
            int idx = tid + i * 256;
            int row = idx >> 3, seg = idx & 7;
            int m = m0 + row; if (m > NODES - 1) m = NODES - 1;
            cp_async16(base + row * 160 + seg * 16,
                       g_Ah + (size_t)m * 256 + k0 + seg * 8);
        }
#pragma unroll
        for (int i = 0; i < 8; i++) {           // B: 256 rows x 8 segs = 2048 slots
            int idx = tid + i * 256;
            int row = idx >> 3, seg = idx & 7;
            cp_async16(base + BG_A_B + row * 160 + seg * 16,
                       g_Wch + (size_t)(n0 + row) * 256 + k0 + seg * 8);
        }
        cp_commit();
    };

    load_chunk(0, 0);

    for (int c = 0; c < 4; ++c) {
        const int s = c & 1;
        if (c + 1 < 4) { load_chunk(c + 1, s ^ 1); cp_wait<1>(); }
        else cp_wait<0>();
        __syncthreads();

        const char* As = smc + s * BG_STGB;
        const char* Bs = As + BG_A_B;
#pragma unroll
        for (int kk = 0; kk < 4; kk++) {
            uint32_t af[4][4], bf[8][2];
#pragma unroll
            for (int mt = 0; mt < 4; mt++) {
                const char* p = As + (wm * 64 + mt * 16 + qr) * 160 + kk * 32 + qc * 8;
                uint2 v0 = *(const uint2*)p;             // row qr:   (a0 | a2)
                uint2 v1 = *(const uint2*)(p + 8 * 160); // row qr+8: (a1 | a3)
                af[mt][0] = v0.x; af[mt][1] = v1.x;
                af[mt][2] = v0.y; af[mt][3] = v1.y;
            }
#pragma unroll
            for (int nt = 0; nt < 8; nt++) {
                const char* p = Bs + (wn * 64 + nt * 8 + qr) * 160 + kk * 32 + qc * 8;
                uint2 v = *(const uint2*)p;              // (b0 | b1)
                bf[nt][0] = v.x; bf[nt][1] = v.y;
            }
#pragma unroll
            for (int mt = 0; mt < 4; mt++)
#pragma unroll
                for (int nt = 0; nt < 8; nt++)
                    mma_f16(acc[mt][nt], af[mt], bf[nt]);
        }
        __syncthreads();
    }

    // epilogue -> g_Rh fp16 (full N=512 covered by 2 n-tiles)
#pragma unroll
    for (int mt = 0; mt < 4; mt++) {
#pragma unroll
        for (int nt = 0; nt < 8; nt++) {
            int rg = m0 + wm * 64 + mt * 16 + qr;
            int cg = n0 + wn * 64 + nt * 8 + qc * 2;
#pragma unroll
            for (int h = 0; h < 2; h++) {
                int r = rg + h * 8;
                if (r < NODES) {
                    *(__half2*)(g_Rh + (size_t)r * 512 + cg) =
                        __floats2half2_rn(acc[mt][nt][h * 2], acc[mt][nt][h * 2 + 1]);
                }
            }
        }
    }
}

// ---------------- small fp16 GEMM (layers 2/3): C = A[M,K] @ Bm[N,K]^T ----------------
// TM x TN tile, 8 warps 2x4, warp tile (TM/2) x (TN/4). k-chunk 64 halves, 2 stages.
// OUT_MODE: 1 = fp16 k16-permuted out (feeds next fp16 GEMM), 0 = fp32 out.
template <int TM, int TN, bool RELU, int OUT_MODE>
__global__ __launch_bounds__(256, 2) void f16_gemm_small(
    const __half* __restrict__ A, const __half* __restrict__ Bm,
    __half* __restrict__ Ch, float* __restrict__ Cf,
    int M, int N, int K)
{
    constexpr int MT = TM / 32;
    constexpr int NT = TN / 32;
    constexpr int A_B = TM * 160;
    constexpr int B_B = TN * 160;
    constexpr int STGB = A_B + B_B;
    extern __shared__ char smc[];
    const uint32_t smA = smem_u32(smc);
    const int tid = threadIdx.x;
    const int lane = tid & 31, wid = tid >> 5;
    const int wm = wid & 1, wn = wid >> 1;
    const int qr = lane >> 2, qc = lane & 3;
    const int m0 = blockIdx.y * TM, n0 = blockIdx.x * TN;

    float acc[MT][NT][4];
#pragma unroll
    for (int mt = 0; mt < MT; mt++)
#pragma unroll
        for (int nt = 0; nt < NT; nt++)
#pragma unroll
            for (int r = 0; r < 4; r++) acc[mt][nt][r] = 0.f;

    const int NKC = K >> 6;

    auto load_chunk = [&](int c, int s) {
        const int k0 = c * 64;
        const uint32_t base = smA + s * STGB;
#pragma unroll
        for (int i = 0; i < TM * 8 / 256; i++) {
            int idx = tid + i * 256;
            int row = idx >> 3, seg = idx & 7;
            int m = m0 + row; if (m > M - 1) m = M - 1;
            cp_async16(base + row * 160 + seg * 16, A + (size_t)m * K + k0 + seg * 8);
        }
#pragma unroll
        for (int i = 0; i < TN * 8 / 256; i++) {
            int idx = tid + i * 256;
            int row = idx >> 3, seg = idx & 7;
            int n = n0 + row; if (n > N - 1) n = N - 1;
            cp_async16(base + A_B + row * 160 + seg * 16, Bm + (size_t)n * K + k0 + seg * 8);
        }
        cp_commit();
    };

    load_chunk(0, 0);

    for (int c = 0; c < NKC; ++c) {
        const int s = c & 1;
        if (c + 1 < NKC) { load_chunk(c + 1, s ^ 1); cp_wait<1>(); }
        else cp_wait<0>();
        __syncthreads();

        const char* As = smc + s * STGB;
        const char* Bs = As + A_B;
#pragma unroll
        for (int kk = 0; kk < 4; kk++) {
            uint32_t af[MT][4], bf[NT][2];
#pragma unroll
            for (int mt = 0; mt < MT; mt++) {
                const char* p = As + (wm * (TM / 2) + mt * 16 + qr) * 160 + kk * 32 + qc * 8;
                uint2 v0 = *(const uint2*)p;
                uint2 v1 = *(const uint2*)(p + 8 * 160);
                af[mt][0] = v0.x; af[mt][1] = v1.x;
                af[mt][2] = v0.y; af[mt][3] = v1.y;
            }
#pragma unroll
            for (int nt = 0; nt < NT; nt++) {
                const char* p = Bs + (wn * (TN / 4) + nt * 8 + qr) * 160 + kk * 32 + qc * 8;
                uint2 v = *(const uint2*)p;
                bf[nt][0] = v.x; bf[nt][1] = v.y;
            }
#pragma unroll
            for (int mt = 0; mt < MT; mt++)
#pragma unroll
                for (int nt = 0; nt < NT; nt++)
                    mma_f16(acc[mt][nt], af[mt], bf[nt]);
        }
        __syncthreads();
    }

#pragma unroll
    for (int mt = 0; mt < MT; mt++) {
#pragma unroll
        for (int nt = 0; nt < NT; nt++) {
            int rg = m0 + wm * (TM / 2) + mt * 16 + qr;
            int cg = n0 + wn * (TN / 4) + nt * 8 + qc * 2;
#pragma unroll
            for (int h = 0; h < 2; h++) {
                int r = rg + h * 8;
                if (r >= M) continue;
                float a = acc[mt][nt][h * 2], b = acc[mt][nt][h * 2 + 1];
                if (RELU) { a = fmaxf(a, 0.f); b = fmaxf(b, 0.f); }
                if (OUT_MODE == 1) {
                    // fwd16 keeps even/odd pairs adjacent
                    *(__half2*)(Ch + (size_t)r * N + fwd16(cg)) = __floats2half2_rn(a, b);
                } else {
                    *(float2*)(Cf + (size_t)r * N + cg) = make_float2(a, b);
                }
            }
        }
    }
}

// ---------------- gather + reduce (R8 core; fp16 k16-permuted output) ----------------
__global__ __launch_bounds__(128) void gather_kernel(
    const int* __restrict__ T0, const int* __restrict__ T1, const int* __restrict__ T2)
{
    __shared__ __align__(16) float   redA[3][32][8];
    __shared__ __align__(16) __half2 redP[3][32][4];
    __shared__ const char* sP1[NF1];
    __shared__ const char* sP2[NF1 * NF2];
    const int b = blockIdx.x;
    const int t = threadIdx.x;
    const char* Rb = (const char*)g_Rh;

    if (t < NF1) sP1[t] = Rb + (size_t)T1[b * NF1 + t] * 1024;
    for (int i = t; i < NF1 * NF2; i += 128) sP2[i] = Rb + (size_t)T2[b * NF1 * NF2 + i] * 1024;
    __syncthreads();

    const int cg = t & 31, fg = t >> 5;
    const int qoff = cg * 16;
    const int poff = 512 + cg * 16;
    const int f0 = (fg == 0) ? 0 : (1 + fg * 6);
    const int f1 = 1 + (fg + 1) * 6;

    __half2 pacc[4];
#pragma unroll
    for (int i = 0; i < 4; i++) pacc[i] = __floats2half2_rn(0.f, 0.f);
    for (int f = f0; f < f1; f++) {
        uint4 v = *(const uint4*)(sP1[f] + poff);
        pacc[0] = __hadd2(pacc[0], *(__half2*)&v.x);
        pacc[1] = __hadd2(pacc[1], *(__half2*)&v.y);
        pacc[2] = __hadd2(pacc[2], *(__half2*)&v.z);
        pacc[3] = __hadd2(pacc[3], *(__half2*)&v.w);
    }

    float a[8];
#pragma unroll
    for (int i = 0; i < 8; i++) a[i] = 0.f;
#pragma unroll 1
    for (int f = f0; f < f1; f++) {
        uint4 qv = *(const uint4*)(sP1[f] + qoff);
        __half2 sA[4], sB[4];
#pragma unroll
        for (int i = 0; i < 4; i++) { sA[i] = __floats2half2_rn(0.f, 0.f); sB[i] = sA[i]; }
#pragma unroll
        for (int j = 0; j < NF2; j += 2) {
            uint4 u = *(const uint4*)(sP2[f * NF2 + j] + poff);
            uint4 w = *(const uint4*)(sP2[f * NF2 + j + 1] + poff);
            sA[0] = __hadd2(sA[0], *(__half2*)&u.x);
            sA[1] = __hadd2(sA[1], *(__half2*)&u.y);
            sA[2] = __hadd2(sA[2], *(__half2*)&u.z);
            sA[3] = __hadd2(sA[3], *(__half2*)&u.w);
            sB[0] = __hadd2(sB[0], *(__half2*)&w.x);
            sB[1] = __hadd2(sB[1], *(__half2*)&w.y);
            sB[2] = __hadd2(sB[2], *(__half2*)&w.z);
            sB[3] = __hadd2(sB[3], *(__half2*)&w.w);
        }
        const uint32_t* qh = (const uint32_t*)&qv;
#pragma unroll
        for (int i = 0; i < 4; i++) {
            float2 s0 = __half22float2(sA[i]);
            float2 s1 = __half22float2(sB[i]);
            float2 q  = __half22float2(*(__half2*)&qh[i]);
            float sx = s0.x + s1.x, sy = s0.y + s1.y;
            a[2 * i]     += fmaxf(fmaf(sx, 0.1f, q.x), 0.f);
            a[2 * i + 1] += fmaxf(fmaf(sy, 0.1f, q.y), 0.f);
        }
    }

    if (fg > 0) {
#pragma unroll
        for (int i = 0; i < 4; i++) redP[fg - 1][cg][i] = pacc[i];
        *(float4*)&redA[fg - 1][cg][0] = make_float4(a[0], a[1], a[2], a[3]);
        *(float4*)&redA[fg - 1][cg][4] = make_float4(a[4], a[5], a[6], a[7]);
    }
    __syncthreads();
    if (fg == 0) {
#pragma unroll
        for (int r = 0; r < 3; r++) {
#pragma unroll
            for (int i = 0; i < 4; i++) pacc[i] = __hadd2(pacc[i], redP[r][cg][i]);
            float4 x = *(const float4*)&redA[r][cg][0];
            float4 y = *(const float4*)&redA[r][cg][4];
            a[0] += x.x; a[1] += x.y; a[2] += x.z; a[3] += x.w;
            a[4] += y.x; a[5] += y.y; a[6] += y.z; a[7] += y.w;
        }
        uint4 q0v = *(const uint4*)(Rb + (size_t)T0[b] * 1024 + qoff);
        const uint32_t* qh = (const uint32_t*)&q0v;
        float h0[8], h1[8];
#pragma unroll
        for (int i = 0; i < 4; i++) {
            float2 p = __half22float2(pacc[i]);
            float2 q = __half22float2(*(__half2*)&qh[i]);
            h0[2 * i]     = fmaxf(fmaf(p.x, 1.f / 25.f, q.x), 0.f);
            h0[2 * i + 1] = fmaxf(fmaf(p.y, 1.f / 25.f, q.y), 0.f);
            h1[2 * i]     = a[2 * i] * (1.f / 25.f);
            h1[2 * i + 1] = a[2 * i + 1] * (1.f / 25.f);
        }
        // fp16 store, k16-permuted: pairs (i, i+1) stay adjacent under fwd16
        const int base = cg * 8;
        __half* Cr = g_Ch + b * 512;
#pragma unroll
        for (int i = 0; i < 8; i += 2) {
            int d = fwd16(base + i);
            *(__half2*)(Cr + d)       = __floats2half2_rn(h0[i], h0[i + 1]);
            *(__half2*)(Cr + 256 + d) = __floats2half2_rn(h1[i], h1[i + 1]);
        }
    }
}

// ---------------- launch ----------------
static constexpr int SM_L2 = 2 * (32 + 128) * 160;   // 51200
static constexpr int SM_L3 = 2 * (32 + 64) * 160;    // 30720

extern "C" void kernel_launch(void* const* d_in, const int* in_sizes, int n_in,
                              void* d_out, int out_size)
{
    const int* T0 = (const int*)d_in[0];
    const int* T1 = (const int*)d_in[1];
    const int* T2 = (const int*)d_in[2];
    const float* emb = (const float*)d_in[3];
    const float* W1 = (const float*)d_in[4];
    const float* W2 = (const float*)d_in[5];
    const float* W3 = (const float*)d_in[6];
    float* out = (float*)d_out;

    void *pW2, *pW3, *pC, *pE;
    cudaGetSymbolAddress(&pW2, g_W2h);
    cudaGetSymbolAddress(&pW3, g_W3h);
    cudaGetSymbolAddress(&pC, g_Ch);
    cudaGetSymbolAddress(&pE, g_Eh);

    cudaFuncSetAttribute((const void*)f16_gemm_big,
                         cudaFuncAttributeMaxDynamicSharedMemorySize, BG_SMEM);
    cudaFuncSetAttribute((const void*)f16_gemm_small<32, 128, true, 1>,
                         cudaFuncAttributeMaxDynamicSharedMemorySize, SM_L2);
    cudaFuncSetAttribute((const void*)f16_gemm_small<32, 64, false, 0>,
                         cudaFuncAttributeMaxDynamicSharedMemorySize, SM_L3);

    // 1) convert weights + emb to fp16, k16-permuted
    conv_all<<<(278528 + NODES * 16 + 255) / 256, 256>>>(W1, W2, W3, emb);

    // 2) R = emb @ Wcat^T -> g_Rh fp16 (128x256 tiles, 64x64 warp tiles)
    {
        dim3 grid(2, (NODES + 127) / 128);
        f16_gemm_big<<<grid, 256, BG_SMEM>>>();
    }

    // 3) gather + reduce -> g_Ch [4096, 512] fp16 k16-permuted
    gather_kernel<<<BATCH, 128>>>(T0, T1, T2);

    // 4) E = relu(C @ W2^T) : [4096, 256], K=512 -> g_Eh fp16 k16-permuted
    {
        dim3 grid(2, BATCH / 32);
        f16_gemm_small<32, 128, true, 1><<<grid, 256, SM_L2>>>(
            (const __half*)pC, (const __half*)pW2, (__half*)pE, nullptr, BATCH, 256, 512);
    }

    // 5) scores = E @ W3^T : [4096, 64], K=256 -> out fp32
    {
        dim3 grid(1, BATCH / 32);
        f16_gemm_small<32, 64, false, 0><<<grid, 256, SM_L3>>>(
            (const __half*)pE, (const __half*)pW3, nullptr, out, BATCH, 64, 256);
    }
}